// round 1
// baseline (speedup 1.0000x reference)
#include <cuda_runtime.h>
#include <cuda_bf16.h>

// Problem constants: B=16, S=512, F=512, H=8, D=512, N_PROJ=H*D=4096
// Scratch: Q/K/V projections [B*S, 4096] fp32 and scores [H*B, 512, 512] fp32.

__device__ float g_Q[16 * 512 * 4096];
__device__ float g_K[16 * 512 * 4096];
__device__ float g_V[16 * 512 * 4096];
__device__ float g_P[8 * 16 * 512 * 512];

// ---------------------------------------------------------------------------
// Tiled fp32 GEMM core: one block computes a 128x128 tile of C.
//   C[m,n] = sum_k A[m,k] * B'[k,n]
//   BT=false: B' = Bm accessed as Bm[k*ldb + n]   (K-major / NN)
//   BT=true : B' = Bm accessed as Bm[n*ldb + k]   (N-major / NT, i.e. C=A*B^T)
// 256 threads, each computes an 8x8 micro-tile. BK=16. No bounds checks:
// all dimensions used here are multiples of 128 (and K multiple of 16).
// ---------------------------------------------------------------------------
template <bool BT>
__device__ __forceinline__ void sgemm_tile(const float* __restrict__ A,
                                           const float* __restrict__ Bm,
                                           float* __restrict__ C,
                                           int K, int lda, int ldb, int ldc)
{
    __shared__ float As[16][132];  // [k][m], padded row (132*4B = 33*16B, keeps 16B align)
    __shared__ float Bs[16][132];  // [k][n]

    const int tid = threadIdx.x;        // 0..255
    const int tx  = tid & 15;           // micro-tile col group
    const int ty  = tid >> 4;           // micro-tile row group
    const int brow = blockIdx.y * 128;
    const int bcol = blockIdx.x * 128;

    // A-load mapping (also used for NT B-load): slot covers (row, 4 k's)
    const int lrow = tid >> 2;          // 0..63
    const int lkc  = (tid & 3) * 4;     // 0,4,8,12

    // NN B-load mapping: (k, 4 n's)
    const int lbk  = tid >> 5;          // 0..7
    const int lbn  = (tid & 31) * 4;    // 0..124

    float acc[8][8];
#pragma unroll
    for (int i = 0; i < 8; i++)
#pragma unroll
        for (int j = 0; j < 8; j++) acc[i][j] = 0.0f;

    for (int k0 = 0; k0 < K; k0 += 16) {
        // ---- load A tile [128 m x 16 k], transpose into As[k][m] ----
#pragma unroll
        for (int i = 0; i < 2; i++) {
            const int row = lrow + i * 64;
            const float4 v = *reinterpret_cast<const float4*>(
                &A[(size_t)(brow + row) * lda + k0 + lkc]);
            As[lkc + 0][row] = v.x;
            As[lkc + 1][row] = v.y;
            As[lkc + 2][row] = v.z;
            As[lkc + 3][row] = v.w;
        }
        // ---- load B tile into Bs[k][n] ----
        if (BT) {
#pragma unroll
            for (int i = 0; i < 2; i++) {
                const int n = lrow + i * 64;
                const float4 v = *reinterpret_cast<const float4*>(
                    &Bm[(size_t)(bcol + n) * ldb + k0 + lkc]);
                Bs[lkc + 0][n] = v.x;
                Bs[lkc + 1][n] = v.y;
                Bs[lkc + 2][n] = v.z;
                Bs[lkc + 3][n] = v.w;
            }
        } else {
#pragma unroll
            for (int i = 0; i < 2; i++) {
                const int kk = lbk + i * 8;
                const float4 v = *reinterpret_cast<const float4*>(
                    &Bm[(size_t)(k0 + kk) * ldb + bcol + lbn]);
                *reinterpret_cast<float4*>(&Bs[kk][lbn]) = v;
            }
        }
        __syncthreads();

        // ---- compute ----
#pragma unroll
        for (int k = 0; k < 16; k++) {
            float a[8], b[8];
#pragma unroll
            for (int i = 0; i < 8; i++) a[i] = As[k][ty * 8 + i];
#pragma unroll
            for (int j = 0; j < 8; j++) b[j] = Bs[k][tx * 8 + j];
#pragma unroll
            for (int i = 0; i < 8; i++)
#pragma unroll
                for (int j = 0; j < 8; j++)
                    acc[i][j] = fmaf(a[i], b[j], acc[i][j]);
        }
        __syncthreads();
    }

    // ---- writeback ----
#pragma unroll
    for (int i = 0; i < 8; i++) {
        float4* cp = reinterpret_cast<float4*>(
            &C[(size_t)(brow + ty * 8 + i) * ldc + bcol + tx * 8]);
        cp[0] = make_float4(acc[i][0], acc[i][1], acc[i][2], acc[i][3]);
        cp[1] = make_float4(acc[i][4], acc[i][5], acc[i][6], acc[i][7]);
    }
}

// ---------------------------------------------------------------------------
// Kernel 1: QKV projections. C[8192,4096] = x[8192,512] @ W[512,4096], z selects W.
// ---------------------------------------------------------------------------
__global__ void proj_kernel(const float* __restrict__ x,
                            const float* __restrict__ wq,
                            const float* __restrict__ wk,
                            const float* __restrict__ wv)
{
    const float* W = (blockIdx.z == 0) ? wq : (blockIdx.z == 1) ? wk : wv;
    float* C       = (blockIdx.z == 0) ? g_Q : (blockIdx.z == 1) ? g_K : g_V;
    sgemm_tile<false>(x, W, C, 512, 512, 4096, 4096);
}

// ---------------------------------------------------------------------------
// Kernel 2: scores[h,b] = Q_hb @ K_hb^T   ([512,512] each), z = h*16 + b
// Q_hb[i,d] = g_Q[(b*512+i)*4096 + h*512 + d]
// ---------------------------------------------------------------------------
__global__ void qk_kernel()
{
    const int z = blockIdx.z;
    const int h = z >> 4;
    const int b = z & 15;
    const float* A  = g_Q + (size_t)b * 512 * 4096 + h * 512;
    const float* Bm = g_K + (size_t)b * 512 * 4096 + h * 512;
    float* C        = g_P + (size_t)z * 512 * 512;
    sgemm_tile<true>(A, Bm, C, 512, 4096, 4096, 512);
}

// ---------------------------------------------------------------------------
// Kernel 3: row-wise softmax over g_P rows of length 512. One block per row.
// ---------------------------------------------------------------------------
__global__ void softmax_kernel()
{
    float* p = g_P + (size_t)blockIdx.x * 512;
    const int t = threadIdx.x;  // 0..255

    float2 v = reinterpret_cast<float2*>(p)[t];

    __shared__ float red[8];

    // max reduction
    float m = fmaxf(v.x, v.y);
#pragma unroll
    for (int o = 16; o > 0; o >>= 1) m = fmaxf(m, __shfl_xor_sync(0xFFFFFFFFu, m, o));
    if ((t & 31) == 0) red[t >> 5] = m;
    __syncthreads();
    m = red[0];
#pragma unroll
    for (int i = 1; i < 8; i++) m = fmaxf(m, red[i]);
    __syncthreads();

    const float e0 = __expf(v.x - m);
    const float e1 = __expf(v.y - m);

    // sum reduction
    float s = e0 + e1;
#pragma unroll
    for (int o = 16; o > 0; o >>= 1) s += __shfl_xor_sync(0xFFFFFFFFu, s, o);
    if ((t & 31) == 0) red[t >> 5] = s;
    __syncthreads();
    s = red[0];
#pragma unroll
    for (int i = 1; i < 8; i++) s += red[i];

    const float inv = 1.0f / s;
    reinterpret_cast<float2*>(p)[t] = make_float2(e0 * inv, e1 * inv);
}

// ---------------------------------------------------------------------------
// Kernel 4: out_hb = P_hb @ V_hb, written to out[b, i, h*512 + d] (ldc=4096)
// ---------------------------------------------------------------------------
__global__ void pv_kernel(float* __restrict__ out)
{
    const int z = blockIdx.z;
    const int h = z >> 4;
    const int b = z & 15;
    const float* A  = g_P + (size_t)z * 512 * 512;
    const float* Bm = g_V + (size_t)b * 512 * 4096 + h * 512;
    float* C        = out + (size_t)b * 512 * 4096 + h * 512;
    sgemm_tile<false>(A, Bm, C, 512, 512, 4096, 4096);
}

extern "C" void kernel_launch(void* const* d_in, const int* in_sizes, int n_in,
                              void* d_out, int out_size)
{
    const float* x  = (const float*)d_in[0];
    const float* wq = (const float*)d_in[1];
    const float* wk = (const float*)d_in[2];
    const float* wv = (const float*)d_in[3];
    float* out = (float*)d_out;

    proj_kernel<<<dim3(32, 64, 3), 256>>>(x, wq, wk, wv);   // Q,K,V
    qk_kernel<<<dim3(4, 4, 128), 256>>>();                  // scores
    softmax_kernel<<<65536, 256>>>();                       // softmax in-place
    pv_kernel<<<dim3(4, 4, 128), 256>>>(out);               // P @ V -> out
}

// round 3
// speedup vs baseline: 1.3975x; 1.3975x over previous
#include <cuda_runtime.h>
#include <cstdint>

// ---------------------------------------------------------------------------
// Problem: B=16, S=512, F=512, H=8, D=512.
// Scratch (device globals):
//   g_Q/g_K/g_V : projections [8192, 4096] fp32
//   g_VT        : V transposed per (h,b): [128][512 d][512 j]
//   g_P         : attention scores [128][512][512]
//   g_WT        : W^T for q,k,v: [3][4096][512]
// ---------------------------------------------------------------------------
__device__ float g_Q[16 * 512 * 4096];
__device__ float g_K[16 * 512 * 4096];
__device__ float g_V[16 * 512 * 4096];
__device__ float g_VT[128 * 512 * 512];
__device__ float g_P[128 * 512 * 512];
__device__ float g_WT[3 * 4096 * 512];

// ===========================================================================
// Helpers
// ===========================================================================
__device__ __forceinline__ uint32_t smem_u32(const void* p) {
    uint32_t a;
    asm("{ .reg .u64 t; cvta.to.shared.u64 t, %1; cvt.u32.u64 %0, t; }"
        : "=r"(a) : "l"(p));
    return a;
}

__device__ __forceinline__ void cp16(uint32_t dst, const void* src) {
    asm volatile("cp.async.cg.shared.global [%0], [%1], 16;"
                 :: "r"(dst), "l"(src) : "memory");
}
#define CP_COMMIT() asm volatile("cp.async.commit_group;" ::: "memory")
#define CP_WAIT2()  asm volatile("cp.async.wait_group 2;" ::: "memory")

// split fp32 -> (hi, lo) tf32 bit patterns
__device__ __forceinline__ void split_tf32(float x, uint32_t& h, uint32_t& l) {
    asm("cvt.rna.tf32.f32 %0, %1;" : "=r"(h) : "f"(x));
    float lf = x - __uint_as_float(h);
    asm("cvt.rna.tf32.f32 %0, %1;" : "=r"(l) : "f"(lf));
}

// D += A * B  (m16n8k8 tf32, row.col)
__device__ __forceinline__ void mma8(float* c, const uint32_t* a, const uint32_t* b) {
    asm volatile(
        "mma.sync.aligned.m16n8k8.row.col.f32.tf32.tf32.f32 "
        "{%0,%1,%2,%3}, {%4,%5,%6,%7}, {%8,%9}, {%0,%1,%2,%3};"
        : "+f"(c[0]), "+f"(c[1]), "+f"(c[2]), "+f"(c[3])
        : "r"(a[0]), "r"(a[1]), "r"(a[2]), "r"(a[3]), "r"(b[0]), "r"(b[1]));
}

// ===========================================================================
// NT GEMM, tensor cores via mma.sync + 3xTF32 emulation.
//   C[128 x 256 tile] = A[M,512] @ B[N,512]^T   (row-major, K contiguous)
// 256 threads = 8 warps, warp grid 2(M) x 4(N), warp tile 64x64.
// SMEM: raw fp32, 4-stage cp.async pipeline, k-block 32.
// Stage: A 128x32 (row stride 36 fl) = 18432B, B 256x32 = 36864B -> 55296B.
// ===========================================================================
#define KB        32
#define NKB       16
#define NSTG      4
#define STAGE     55296
#define B_OFF     18432
#define GEMM_SMEM (NSTG * STAGE)   // 221184 bytes

__device__ __forceinline__ void gemm_nt(const float* __restrict__ A, int lda,
                                        const float* __restrict__ B, int ldb,
                                        float* __restrict__ C, int ldc)
{
    extern __shared__ char smc[];
    const uint32_t sa = smem_u32(smc);

    const int tid = threadIdx.x;
    const int wid = tid >> 5;
    const int lid = tid & 31;
    const int wr  = wid >> 2;        // 0..1  (M)
    const int wc  = wid & 3;         // 0..3  (N)
    const int g   = lid >> 2;        // 0..7
    const int tg  = lid & 3;         // 0..3

    const float* Ab = A + (size_t)(blockIdx.y * 128) * lda;
    const float* Bb = B + (size_t)(blockIdx.x * 256) * ldb;

    // ---- producer: one stage of cp.async (48KB raw fp32) ----
    auto load_stage = [&](int buf, int kb) {
        const uint32_t dbase = sa + buf * STAGE;
        const int kc = kb * KB;
#pragma unroll
        for (int i = 0; i < 4; ++i) {               // A: ids 0..1023
            const int id = tid + (i << 8);
            const int row = id >> 3, c = id & 7;
            cp16(dbase + row * 144 + c * 16, Ab + (size_t)row * lda + kc + c * 4);
        }
#pragma unroll
        for (int i = 0; i < 8; ++i) {               // B: ids 0..2047
            const int id = tid + (i << 8);
            const int row = id >> 3, c = id & 7;
            cp16(dbase + B_OFF + row * 144 + c * 16, Bb + (size_t)row * ldb + kc + c * 4);
        }
    };

    float acc[4][8][4];
#pragma unroll
    for (int mt = 0; mt < 4; ++mt)
#pragma unroll
        for (int nt = 0; nt < 8; ++nt)
#pragma unroll
            for (int i = 0; i < 4; ++i) acc[mt][nt][i] = 0.0f;

    // preload 3 stages
    load_stage(0, 0); CP_COMMIT();
    load_stage(1, 1); CP_COMMIT();
    load_stage(2, 2); CP_COMMIT();

#pragma unroll 1
    for (int kb = 0; kb < NKB; ++kb) {
        CP_WAIT2();
        __syncthreads();

        const int buf = kb & (NSTG - 1);
        const float* As = (const float*)(smc + buf * STAGE);
        const float* Bs = (const float*)(smc + buf * STAGE + B_OFF);

#pragma unroll
        for (int ks = 0; ks < 4; ++ks) {
            // A frags (hi+lo) for 4 m-tiles
            uint32_t ah[4][4], al[4][4];
#pragma unroll
            for (int mt = 0; mt < 4; ++mt) {
                const float* p = As + (wr * 64 + mt * 16 + g) * 36 + ks * 8 + tg;
                float r0 = p[0], r1 = p[288], r2 = p[4], r3 = p[292];  // 288=8*36
                split_tf32(r0, ah[mt][0], al[mt][0]);
                split_tf32(r1, ah[mt][1], al[mt][1]);
                split_tf32(r2, ah[mt][2], al[mt][2]);
                split_tf32(r3, ah[mt][3], al[mt][3]);
            }
#pragma unroll
            for (int nt = 0; nt < 8; ++nt) {
                const float* q = Bs + (wc * 64 + nt * 8 + g) * 36 + ks * 8 + tg;
                float s0 = q[0], s1 = q[4];
                uint32_t bh[2], bl[2];
                split_tf32(s0, bh[0], bl[0]);
                split_tf32(s1, bh[1], bl[1]);
                // 3 passes over m-tiles: same accumulator revisited at distance 4
#pragma unroll
                for (int mt = 0; mt < 4; ++mt) mma8(acc[mt][nt], ah[mt], bh);
#pragma unroll
                for (int mt = 0; mt < 4; ++mt) mma8(acc[mt][nt], ah[mt], bl);
#pragma unroll
                for (int mt = 0; mt < 4; ++mt) mma8(acc[mt][nt], al[mt], bh);
            }
        }

        if (kb + 3 < NKB) load_stage((kb + 3) & (NSTG - 1), kb + 3);
        CP_COMMIT();
    }

    // ---- epilogue ----
    const int rbase = blockIdx.y * 128 + wr * 64 + g;
    const int cbase = blockIdx.x * 256 + wc * 64 + tg * 2;
#pragma unroll
    for (int mt = 0; mt < 4; ++mt) {
#pragma unroll
        for (int nt = 0; nt < 8; ++nt) {
            const int r = rbase + mt * 16;
            const int c = cbase + nt * 8;
            *reinterpret_cast<float2*>(&C[(size_t)r * ldc + c]) =
                make_float2(acc[mt][nt][0], acc[mt][nt][1]);
            *reinterpret_cast<float2*>(&C[(size_t)(r + 8) * ldc + c]) =
                make_float2(acc[mt][nt][2], acc[mt][nt][3]);
        }
    }
}

// ===========================================================================
// GEMM wrappers
// ===========================================================================
__global__ void __launch_bounds__(256, 1)
proj_mm(const float* __restrict__ x)
{
    const int z = blockIdx.z;                 // 0:Q 1:K 2:V
    const float* B = g_WT + (size_t)z * 4096 * 512;
    float* C = (z == 0) ? g_Q : (z == 1) ? g_K : g_V;
    gemm_nt(x, 512, B, 512, C, 4096);
}

__global__ void __launch_bounds__(256, 1)
qk_mm()
{
    const int z = blockIdx.z;                 // h*16 + b
    const int h = z >> 4, b = z & 15;
    const float* A = g_Q + (size_t)b * 512 * 4096 + h * 512;
    const float* B = g_K + (size_t)b * 512 * 4096 + h * 512;
    float* C = g_P + (size_t)z * 512 * 512;
    gemm_nt(A, 4096, B, 4096, C, 512);
}

__global__ void __launch_bounds__(256, 1)
pv_mm(float* __restrict__ out)
{
    const int z = blockIdx.z;
    const int h = z >> 4, b = z & 15;
    const float* A = g_P + (size_t)z * 512 * 512;
    const float* B = g_VT + (size_t)z * 512 * 512;
    float* C = out + (size_t)b * 512 * 4096 + h * 512;
    gemm_nt(A, 512, B, 512, C, 4096);
}

// ===========================================================================
// Transposes
// ===========================================================================
__global__ void wt_kernel(const float* __restrict__ wq,
                          const float* __restrict__ wk,
                          const float* __restrict__ wv)
{
    __shared__ float t[32][33];
    const int z = blockIdx.z;
    const float* W = (z == 0) ? wq : (z == 1) ? wk : wv;   // [512, 4096]
    float* WT = g_WT + (size_t)z * 4096 * 512;              // [4096, 512]
    const int n0 = blockIdx.x * 32, k0 = blockIdx.y * 32;
    const int tx = threadIdx.x, ty = threadIdx.y;
#pragma unroll
    for (int i = 0; i < 4; ++i)
        t[ty + i * 8][tx] = W[(size_t)(k0 + ty + i * 8) * 4096 + n0 + tx];
    __syncthreads();
#pragma unroll
    for (int i = 0; i < 4; ++i)
        WT[(size_t)(n0 + ty + i * 8) * 512 + k0 + tx] = t[tx][ty + i * 8];
}

__global__ void vt_kernel()
{
    __shared__ float t[32][33];
    const int z = blockIdx.z;                 // h*16 + b
    const int h = z >> 4, b = z & 15;
    const int j0 = blockIdx.x * 32, d0 = blockIdx.y * 32;
    const int tx = threadIdx.x, ty = threadIdx.y;
#pragma unroll
    for (int i = 0; i < 4; ++i)
        t[ty + i * 8][tx] = g_V[(size_t)(b * 512 + j0 + ty + i * 8) * 4096 + h * 512 + d0 + tx];
    __syncthreads();
    float* VT = g_VT + (size_t)z * 512 * 512;
#pragma unroll
    for (int i = 0; i < 4; ++i)
        VT[(size_t)(d0 + ty + i * 8) * 512 + j0 + tx] = t[tx][ty + i * 8];
}

// ===========================================================================
// Softmax over rows of g_P (length 512), one block per row
// ===========================================================================
__global__ void softmax_kernel()
{
    float* p = g_P + (size_t)blockIdx.x * 512;
    const int t = threadIdx.x;  // 0..255

    float2 v = reinterpret_cast<float2*>(p)[t];
    __shared__ float red[8];

    float m = fmaxf(v.x, v.y);
#pragma unroll
    for (int o = 16; o > 0; o >>= 1) m = fmaxf(m, __shfl_xor_sync(0xFFFFFFFFu, m, o));
    if ((t & 31) == 0) red[t >> 5] = m;
    __syncthreads();
    m = red[0];
#pragma unroll
    for (int i = 1; i < 8; i++) m = fmaxf(m, red[i]);
    __syncthreads();

    const float e0 = __expf(v.x - m);
    const float e1 = __expf(v.y - m);

    float s = e0 + e1;
#pragma unroll
    for (int o = 16; o > 0; o >>= 1) s += __shfl_xor_sync(0xFFFFFFFFu, s, o);
    if ((t & 31) == 0) red[t >> 5] = s;
    __syncthreads();
    s = red[0];
#pragma unroll
    for (int i = 1; i < 8; i++) s += red[i];

    const float inv = 1.0f / s;
    reinterpret_cast<float2*>(p)[t] = make_float2(e0 * inv, e1 * inv);
}

// ===========================================================================
// Launch
// ===========================================================================
extern "C" void kernel_launch(void* const* d_in, const int* in_sizes, int n_in,
                              void* d_out, int out_size)
{
    const float* x  = (const float*)d_in[0];
    const float* wq = (const float*)d_in[1];
    const float* wk = (const float*)d_in[2];
    const float* wv = (const float*)d_in[3];
    float* out = (float*)d_out;

    cudaFuncSetAttribute(proj_mm, cudaFuncAttributeMaxDynamicSharedMemorySize, GEMM_SMEM);
    cudaFuncSetAttribute(qk_mm,   cudaFuncAttributeMaxDynamicSharedMemorySize, GEMM_SMEM);
    cudaFuncSetAttribute(pv_mm,   cudaFuncAttributeMaxDynamicSharedMemorySize, GEMM_SMEM);

    wt_kernel<<<dim3(128, 16, 3), dim3(32, 8)>>>(wq, wk, wv);
    proj_mm<<<dim3(16, 64, 3), 256, GEMM_SMEM>>>(x);       // Q,K,V = x @ W
    vt_kernel<<<dim3(16, 16, 128), dim3(32, 8)>>>();
    qk_mm<<<dim3(2, 4, 128), 256, GEMM_SMEM>>>();          // scores
    softmax_kernel<<<65536, 256>>>();
    pv_mm<<<dim3(2, 4, 128), 256, GEMM_SMEM>>>(out);       // P @ V
}